// round 17
// baseline (speedup 1.0000x reference)
#include <cuda_runtime.h>
#include <math.h>

#define Bq 512
#define Sq 4096
#define Dq 128
#define Vq 6
#define Kq 409

// Precomputed per-token-value tables + producer/consumer flags
__device__ float g_score[Vq];
__device__ float g_attC1[Vq * 64];   // att_v @ C1  (classifier layer-1 fold)
__device__ int   g_done = 0;         // producers completed (0..6)
__device__ int   g_fin  = 0;         // CTAs finished (for flag reset)

// ---------------------------------------------------------------------------
// Per-value precompute, run by CTAs 0..5 inside the main kernel.
// __noinline__ contains its register footprint away from the hot path.
// ---------------------------------------------------------------------------
__device__ __noinline__ void do_precompute(
    int v, int t, float* e, float* h1, float* g1, float* h2, float* att_s,
    const float* __restrict__ emb,
    const float* __restrict__ W1, const float* __restrict__ b1,
    const float* __restrict__ W2, const float* __restrict__ b2,
    const float* __restrict__ W3, const float* __restrict__ b3,
    const float* __restrict__ A1, const float* __restrict__ a1,
    const float* __restrict__ A2, const float* __restrict__ a2,
    const float* __restrict__ C1)
{
    if (t < Dq) e[t] = __ldg(&emb[v * Dq + t]);
    __syncthreads();

    // layer 1: both W1 and A1. 256 threads = 2 mats x 64 neurons x 2 halves.
    {
        const int mat = t >> 7;
        const int n   = (t & 127) >> 1;
        const int p   = t & 1;
        const float* M = mat ? A1 : W1;
        float s = 0.f;
        const int base = p * 64;
        #pragma unroll
        for (int i = 0; i < 64; i++)
            s += e[base + i] * __ldg(&M[(base + i) * 64 + n]);
        s += __shfl_xor_sync(0xffffffff, s, 1);
        if (p == 0) {
            if (mat == 0) h1[n] = fmaxf(s + __ldg(&b1[n]), 0.f);
            else          g1[n] = fmaxf(s + __ldg(&a1[n]), 0.f);
        }
    }
    __syncthreads();

    // layer 2 (W2): 32 neurons x 4 threads (threads 0..127)
    if (t < 128) {
        const int n = t >> 2, p = t & 3;
        float s = 0.f;
        const int base = p * 16;
        #pragma unroll
        for (int i = 0; i < 16; i++)
            s += h1[base + i] * __ldg(&W2[(base + i) * 32 + n]);
        s += __shfl_xor_sync(0xffffffff, s, 1);
        s += __shfl_xor_sync(0xffffffff, s, 2);
        if (p == 0) h2[n] = fmaxf(s + __ldg(&b2[n]), 0.f);
    }
    // A2: 128 outputs x 2 threads
    {
        const int j = t >> 1, p = t & 1;
        float s = 0.f;
        const int base = p * 32;
        #pragma unroll
        for (int i = 0; i < 32; i++)
            s += g1[base + i] * __ldg(&A2[(base + i) * Dq + j]);
        s += __shfl_xor_sync(0xffffffff, s, 1);
        if (p == 0) att_s[j] = s + __ldg(&a2[j]);
    }
    __syncthreads();

    // layer 3: warp 0 -> sigmoid score
    if (t < 32) {
        float z = h2[t] * __ldg(&W3[t]);
        #pragma unroll
        for (int d = 16; d >= 1; d >>= 1) z += __shfl_xor_sync(0xffffffff, z, d);
        if (t == 0) g_score[v] = 1.f / (1.f + expf(-(z + __ldg(&b3[0]))));
    }

    // attC1[v][n] = att_v @ C1[:,n]: 64 neurons x 4 threads
    {
        const int n = t >> 2, p = t & 3;
        float s = 0.f;
        const int base = p * 32;
        #pragma unroll
        for (int i = 0; i < 32; i++)
            s += att_s[base + i] * __ldg(&C1[(base + i) * 64 + n]);
        s += __shfl_xor_sync(0xffffffff, s, 1);
        s += __shfl_xor_sync(0xffffffff, s, 2);
        if (p == 0) g_attC1[v * 64 + n] = s;
    }
    __syncthreads();

    // publish: release fence + done increment
    if (t == 0) {
        asm volatile("fence.release.gpu;" ::: "memory");
        atomicAdd(&g_done, 1);
    }
}

// ---------------------------------------------------------------------------
// Single fused kernel: one CTA per batch row (512 CTAs, 256 threads).
// CTAs 0..5 additionally produce the per-value tables; all CTAs gate on a
// device flag (acquire spin) before consuming them.
// ---------------------------------------------------------------------------
__global__ __launch_bounds__(256, 4) void fused_kernel(
    const int* __restrict__ x,
    const float* __restrict__ emb,
    const float* __restrict__ W1, const float* __restrict__ b1,
    const float* __restrict__ W2, const float* __restrict__ b2,
    const float* __restrict__ W3, const float* __restrict__ b3,
    const float* __restrict__ A1, const float* __restrict__ a1,
    const float* __restrict__ A2, const float* __restrict__ a2,
    const float* __restrict__ C1, const float* __restrict__ c1,
    const float* __restrict__ C2, const float* __restrict__ c2,
    float* __restrict__ out)
{
    const int b = blockIdx.x;
    const int t = threadIdx.x;  // 256 threads
    const int w = t >> 5, l = t & 31;

    __shared__ unsigned long long wtot[8];
    __shared__ float ps[Dq + 64 + 64 + 32 + Dq];  // precompute scratch (CTAs 0..5)

    // ---------- producers: CTAs 0..5 compute tables first ----------
    if (b < Vq) {
        do_precompute(b, t, ps, ps + Dq, ps + Dq + 64, ps + Dq + 128,
                      ps + Dq + 160,
                      emb, W1, b1, W2, b2, W3, b3, A1, a1, A2, a2, C1);
    }

    // ---------- score-independent front half ----------
    const int4* xb = (const int4*)(x + (size_t)b * Sq);

    int4 P[4];
    unsigned long long hist = 0ull;
    #pragma unroll
    for (int i = 0; i < 4; i++) {
        int4 p = xb[t * 4 + i];
        P[i] = p;
        hist += 1ull << (p.x * 10);
        hist += 1ull << (p.y * 10);
        hist += 1ull << (p.z * 10);
        hist += 1ull << (p.w * 10);
    }

    // warp-level packed inclusive scan (10-bit fields)
    unsigned long long run = hist;
    #pragma unroll
    for (int d = 1; d < 32; d <<= 1) {
        unsigned long long o = __shfl_up_sync(0xffffffff, run, d);
        if (l >= d) run += o;
    }
    const unsigned long long excl = run - hist;
    if (l == 31) wtot[w] = run;
    __syncthreads();

    // cross-warp: packed exclusive base (pcnt) + per-value block totals
    unsigned long long pcnt;
    int tot[Vq];
    {
        unsigned long long pre = 0ull, all = 0ull;
        #pragma unroll
        for (int ww = 0; ww < 8; ww++) {
            unsigned long long tw = wtot[ww];
            if (ww < w) pre += tw;
            all += tw;
        }
        pcnt = pre + excl;
        #pragma unroll
        for (int v = 0; v < Vq; v++)
            tot[v] = (int)((all >> (v * 10)) & 0x3FF);
    }

    // ---------- wait for producers (acquire spin by t0, then barrier) ----------
    if (t == 0) {
        int d;
        do {
            asm volatile("ld.acquire.gpu.b32 %0, [%1];"
                         : "=r"(d) : "l"(&g_done) : "memory");
        } while (d != Vq);
    }
    __syncthreads();

    float sc[Vq];
    #pragma unroll
    for (int v = 0; v < Vq; v++) sc[v] = g_score[v];

    // lane-resident score for dynamic gather via shfl
    const int v_me = (l < Vq) ? l : (Vq - 1);
    const float scf = sc[v_me];

    // per-lane rank offset: offraw_l = sum of tot[u] for u preceding v_me
    int offraw_lane = 0;
    #pragma unroll
    for (int u = 0; u < Vq; u++) {
        bool prec = (u != v_me) &&
                    ((sc[u] > sc[v_me]) || (sc[u] == sc[v_me] && u < v_me));
        offraw_lane += prec ? tot[u] : 0;
    }

    // ---------- fused fs-store + compaction (direct global scatter) ----------
    float* fs   = out + Bq + (size_t)Bq * Kq + (size_t)b * Sq;
    float* oidx = out + Bq + (size_t)b * Kq;
    #pragma unroll
    for (int i = 0; i < 4; i++) {
        const int* pv = (const int*)&P[i];
        float4 f;
        float* fp = (float*)&f;
        #pragma unroll
        for (int j = 0; j < 4; j++) {
            const int vv = pv[j];
            fp[j] = __shfl_sync(0xffffffff, scf, vv);
            const int ofr = __shfl_sync(0xffffffff, offraw_lane, vv);
            const int sh = vv * 10;
            const int rank = (int)((pcnt >> sh) & 0x3FF);
            pcnt += 1ull << sh;
            const int pos = ofr + rank;
            if (pos < Kq) oidx[pos] = (float)(t * 16 + i * 4 + j);
        }
        ((float4*)fs)[t * 4 + i] = f;
    }

    // ---------- folded classifier epilogue (warp 0 only) ----------
    if (w == 0) {
        float takef[Vq];
        #pragma unroll
        for (int v = 0; v < Vq; v++) {
            const int ofr = __shfl_sync(0xffffffff, offraw_lane, v);
            takef[v] = (float)max(0, min(Kq - ofr, tot[v]));
        }
        const float invK = 1.f / (float)Kq;
        float zacc = 0.f;
        #pragma unroll
        for (int hh = 0; hh < 2; hh++) {
            const int n = l + hh * 32;
            float s = 0.f;
            #pragma unroll
            for (int v = 0; v < Vq; v++)
                s += takef[v] * g_attC1[v * 64 + n];
            const float h = fmaxf(fmaf(s, invK, c1[n]), 0.f);
            zacc += h * C2[n];
        }
        #pragma unroll
        for (int d = 16; d >= 1; d >>= 1)
            zacc += __shfl_xor_sync(0xffffffff, zacc, d);
        if (l == 0) out[b] = 1.f / (1.f + expf(-(zacc + c2[0])));
    }

    // ---------- flag reset for graph replay (last CTA to finish) ----------
    if (t == 0) {
        int f = atomicAdd(&g_fin, 1);
        if (f == Bq - 1) {
            g_done = 0;
            g_fin  = 0;
        }
    }
}

extern "C" void kernel_launch(void* const* d_in, const int* in_sizes, int n_in,
                              void* d_out, int out_size) {
    const int*   x   = (const int*)d_in[0];
    const float* emb = (const float*)d_in[1];
    const float* W1  = (const float*)d_in[2];
    const float* b1  = (const float*)d_in[3];
    const float* W2  = (const float*)d_in[4];
    const float* b2  = (const float*)d_in[5];
    const float* W3  = (const float*)d_in[6];
    const float* b3  = (const float*)d_in[7];
    const float* A1  = (const float*)d_in[8];
    const float* a1  = (const float*)d_in[9];
    const float* A2  = (const float*)d_in[10];
    const float* a2  = (const float*)d_in[11];
    const float* C1  = (const float*)d_in[12];
    const float* c1  = (const float*)d_in[13];
    const float* C2  = (const float*)d_in[14];
    const float* c2  = (const float*)d_in[15];
    float* out = (float*)d_out;

    fused_kernel<<<Bq, 256>>>(x, emb, W1, b1, W2, b2, W3, b3,
                              A1, a1, A2, a2, C1, c1, C2, c2, out);
}